// round 8
// baseline (speedup 1.0000x reference)
#include <cuda_runtime.h>
#include <cstdint>

#define NATOMS   4096
#define BLOCK_SZ 512
#define BOXF     44.0f
#define INV_BOX  (1.0f / 44.0f)
#define CUT2     (17.5f * 17.5f)

#define T        256                        // tile size (atoms)
#define NTILE    (NATOMS / T)               // 16
#define NPAIR    (NTILE * (NTILE + 1) / 2)  // 136 CTAs -> single wave on 148 SMs
#define TPB      512                        // 16 warps

// deterministic scratch + grid barrier state
__device__ float    g_fpart[NTILE * NATOMS * 3];   // [slot][atom][xyz]
__device__ float    g_ecta[NPAIR];
__device__ unsigned g_done = 0;   // arrival counter (reset by last CTA)
__device__ unsigned g_flag = 0;   // sense-reversing release flag (alternates per launch)

__inline__ __device__ float warp_sum(float v) {
    #pragma unroll
    for (int o = 16; o > 0; o >>= 1) v += __shfl_down_sync(0xffffffffu, v, o);
    return v;
}

// one pair: returns weighted g*r components, accumulates energy
__inline__ __device__ void pm(float dx, float dy, float dz,
                              float a, float c, float dd, float rh, float sg,
                              bool valid, float wbase,
                              float& en, float& gx, float& gy, float& gz)
{
    dx -= rintf(dx * INV_BOX) * BOXF;
    dy -= rintf(dy * INV_BOX) * BOXF;
    dz -= rintf(dz * INV_BOX) * BOXF;
    const float r2 = fmaf(dx, dx, fmaf(dy, dy, dz * dz));

    const bool  ok = valid && (r2 < CUT2);
    const float we = ok ? wbase : 0.0f;
    const float wf = (ok && r2 > 1.0f) ? wbase : 0.0f;

    const float r2c  = fmaxf(r2, 1.0f);
    const float dinv = rsqrtf(r2c);
    const float dij  = r2c * dinv;

    const float invrh = __fdividef(1.0f, rh);
    const float e     = __expf((sg - dij) * invrh);

    const float inv2 = dinv * dinv;
    const float inv6 = inv2 * inv2 * inv2;
    const float inv8 = inv6 * inv2;

    const float ae = a * e;
    const float pe = fmaf(dd, inv8, fmaf(-c, inv6, ae));
    en = fmaf(we, pe, en);                       // unordered pair counted once

    float g = fmaf(6.0f * c, inv8,
                   fmaf(-8.0f * dd, inv8 * inv2,
                        -(ae * invrh) * dinv));
    g *= wf;
    gx = g * dx; gy = g * dy; gz = g * dz;
}

__global__ __launch_bounds__(TPB)
void bmh_tile_kernel(const float* __restrict__ coords,
                     const float* __restrict__ A,
                     const float* __restrict__ C,
                     const float* __restrict__ D,
                     const float* __restrict__ RHO,
                     const float* __restrict__ SIG,
                     float* __restrict__ out)
{
    const int t    = threadIdx.x;
    const int lane = t & 31;
    const int w    = t >> 5;                 // warp 0..15

    // read barrier sense BEFORE any work (strictly precedes our arrival increment)
    const unsigned F = *((volatile unsigned*)&g_flag);

    // decode blockIdx -> tile pair (ti <= tj)
    int k = blockIdx.x, ti = 0, rem = NTILE;
    while (k >= rem) { k -= rem; ++ti; --rem; }
    const int tj   = ti + k;
    const bool diag = (ti == tj);

    // this lane owns columns jc0..jc0+7 of tile tj
    const int jc0 = 8 * lane;
    const int jg0 = tj * T + jc0;
    const float wbase = ((ti >> 1) == (tj >> 1)) ? 1.0f : 2.0f;  // same 512-block?

    // column coords: 24 contiguous floats = 6 float4
    float xj[8], yj[8], zj[8];
    {
        const float4* cf = (const float4*)(coords + 3 * (size_t)jg0);
        float v[24];
        #pragma unroll
        for (int q = 0; q < 6; ++q) {
            const float4 f = __ldg(cf + q);
            v[4 * q + 0] = f.x; v[4 * q + 1] = f.y; v[4 * q + 2] = f.z; v[4 * q + 3] = f.w;
        }
        #pragma unroll
        for (int c = 0; c < 8; ++c) { xj[c] = v[3 * c]; yj[c] = v[3 * c + 1]; zj[c] = v[3 * c + 2]; }
    }
    const int locj0 = jg0 & (BLOCK_SZ - 1);

    __shared__ float frow[T][3];              // row-force results
    __shared__ float fcolp[16][T * 3];        // per-warp column-force partials
    __shared__ float esm[TPB / 32];

    float fjx[8], fjy[8], fjz[8];
    #pragma unroll
    for (int c = 0; c < 8; ++c) { fjx[c] = 0.f; fjy[c] = 0.f; fjz[c] = 0.f; }
    float en = 0.f;

    const size_t rowstart = (size_t)(ti * T) * NATOMS + tj * T + jc0;

    #pragma unroll 2
    for (int s = 0; s < T / 16; ++s) {
        const int i  = s * 16 + w;            // row within tile (warp-exclusive)
        const int ig = ti * T + i;
        const size_t off = rowstart + (size_t)i * NATOMS;

        const float4 aA = __ldg((const float4*)(A   + off));
        const float4 aB = __ldg((const float4*)(A   + off + 4));
        const float4 cA = __ldg((const float4*)(C   + off));
        const float4 cB = __ldg((const float4*)(C   + off + 4));
        const float4 dA = __ldg((const float4*)(D   + off));
        const float4 dB = __ldg((const float4*)(D   + off + 4));
        const float4 rA = __ldg((const float4*)(RHO + off));
        const float4 rB = __ldg((const float4*)(RHO + off + 4));
        const float4 sA = __ldg((const float4*)(SIG + off));
        const float4 sB = __ldg((const float4*)(SIG + off + 4));

        const float xi = __ldg(&coords[3 * ig + 0]);
        const float yi = __ldg(&coords[3 * ig + 1]);
        const float zi = __ldg(&coords[3 * ig + 2]);
        const int loci = ig & (BLOCK_SZ - 1);

        float av[8] = {aA.x, aA.y, aA.z, aA.w, aB.x, aB.y, aB.z, aB.w};
        float cv[8] = {cA.x, cA.y, cA.z, cA.w, cB.x, cB.y, cB.z, cB.w};
        float dv[8] = {dA.x, dA.y, dA.z, dA.w, dB.x, dB.y, dB.z, dB.w};
        float rv[8] = {rA.x, rA.y, rA.z, rA.w, rB.x, rB.y, rB.z, rB.w};
        float sv[8] = {sA.x, sA.y, sA.z, sA.w, sB.x, sB.y, sB.z, sB.w};

        float rx = 0.f, ry = 0.f, rz = 0.f;
        #pragma unroll
        for (int c = 0; c < 8; ++c) {
            float gx, gy, gz;
            const bool ok = (loci != locj0 + c) && (!diag || i < jc0 + c);
            pm(xi - xj[c], yi - yj[c], zi - zj[c],
               av[c], cv[c], dv[c], rv[c], sv[c], ok, wbase, en, gx, gy, gz);
            rx += gx; ry += gy; rz += gz;
            fjx[c] -= gx; fjy[c] -= gy; fjz[c] -= gz;
        }

        rx = warp_sum(rx); ry = warp_sum(ry); rz = warp_sum(rz);
        if (lane == 0) { frow[i][0] = rx; frow[i][1] = ry; frow[i][2] = rz; }
    }

    // stash per-warp column partials
    {
        float* cp = &fcolp[w][jc0 * 3];
        #pragma unroll
        for (int c = 0; c < 8; ++c) {
            cp[3 * c + 0] = fjx[c];
            cp[3 * c + 1] = fjy[c];
            cp[3 * c + 2] = fjz[c];
        }
    }

    en = warp_sum(en);
    if (lane == 0) esm[w] = en;
    __syncthreads();

    if (t < T) {
        float rx = frow[t][0], ry = frow[t][1], rz = frow[t][2];
        if (diag) {
            #pragma unroll
            for (int ww = 0; ww < 16; ++ww) {
                rx += fcolp[ww][t * 3 + 0];
                ry += fcolp[ww][t * 3 + 1];
                rz += fcolp[ww][t * 3 + 2];
            }
        }
        float* dst = g_fpart + ((size_t)tj * NATOMS + ti * T + t) * 3;
        dst[0] = rx; dst[1] = ry; dst[2] = rz;
    } else if (!diag) {
        const int c = t - T;
        float cx = 0.f, cy = 0.f, cz = 0.f;
        #pragma unroll
        for (int ww = 0; ww < 16; ++ww) {
            cx += fcolp[ww][c * 3 + 0];
            cy += fcolp[ww][c * 3 + 1];
            cz += fcolp[ww][c * 3 + 2];
        }
        float* dst = g_fpart + ((size_t)ti * NATOMS + tj * T + c) * 3;
        dst[0] = cx; dst[1] = cy; dst[2] = cz;
    }

    if (t < 32) {
        float v = (t < TPB / 32) ? esm[t] : 0.f;
        v = warp_sum(v);
        if (t == 0) g_ecta[blockIdx.x] = v;
    }

    // ---- grid-wide barrier (single wave: 136 CTAs, all resident) ----
    __syncthreads();          // all CTA writes done
    if (t == 0) {
        __threadfence();      // publish g_fpart / g_ecta
        const unsigned ticket = atomicAdd(&g_done, 1u);
        if (ticket == NPAIR - 1) {
            g_done = 0;       // safe: nobody touches counter until next launch
            __threadfence();
            atomicExch(&g_flag, F ^ 1u);   // release
        } else {
            while (atomicAdd(&g_flag, 0u) == F) __nanosleep(64);
        }
    }
    __syncthreads();
    __threadfence();          // acquire side before reading other CTAs' partials

    // ---- fused reduction: CTAs 0..23 forces (24*512 = 12288 gids), CTA 24 energy ----
    const int b = blockIdx.x;
    if (b < 24) {
        const int gid = b * TPB + t;
        float s = 0.f;
        #pragma unroll
        for (int p = 0; p < NTILE; ++p)
            s += g_fpart[(size_t)p * (NATOMS * 3) + gid];
        out[1 + gid] = s;
    } else if (b == 24) {
        double s = (t < NPAIR) ? (double)g_ecta[t] : 0.0;
        __shared__ double sd[TPB];
        sd[t] = s;
        __syncthreads();
        #pragma unroll
        for (int o = TPB / 2; o > 0; o >>= 1) {
            if (t < o) sd[t] += sd[t + o];
            __syncthreads();
        }
        if (t == 0) out[0] = (float)sd[0];
    }
}

extern "C" void kernel_launch(void* const* d_in, const int* in_sizes, int n_in,
                              void* d_out, int out_size)
{
    const float* coords = (const float*)d_in[0];
    // d_in[1] = q (computed-but-unused upstream; faithfully ignored)
    const float* A   = (const float*)d_in[2];
    const float* C   = (const float*)d_in[3];
    const float* D   = (const float*)d_in[4];
    const float* RHO = (const float*)d_in[5];
    const float* SIG = (const float*)d_in[6];
    float* out = (float*)d_out;

    bmh_tile_kernel<<<NPAIR, TPB>>>(coords, A, C, D, RHO, SIG, out);
}

// round 9
// speedup vs baseline: 1.0430x; 1.0430x over previous
#include <cuda_runtime.h>
#include <cstdint>

#define NATOMS   4096
#define BLOCK_SZ 512
#define BOXF     44.0f
#define INV_BOX  (1.0f / 44.0f)
#define CUT2     (17.5f * 17.5f)

#define T        256                        // tile size (atoms)
#define NTILE    (NATOMS / T)               // 16
#define NPAIR    (NTILE * (NTILE + 1) / 2)  // 136 CTAs -> single wave on 148 SMs
#define TPB      512                        // 16 warps; each warp covers all 256 cols

// deterministic scratch: per-(slot,atom) force partials + per-CTA energy partials
__device__ float g_fpart[NTILE * NATOMS * 3];   // [slot][atom][xyz]
__device__ float g_ecta[NPAIR];

__inline__ __device__ float warp_sum(float v) {
    #pragma unroll
    for (int o = 16; o > 0; o >>= 1) v += __shfl_down_sync(0xffffffffu, v, o);
    return v;
}

// one pair: returns weighted g*r components, accumulates energy
__inline__ __device__ void pm(float dx, float dy, float dz,
                              float a, float c, float dd, float rh, float sg,
                              bool valid, float wbase,
                              float& en, float& gx, float& gy, float& gz)
{
    dx -= rintf(dx * INV_BOX) * BOXF;
    dy -= rintf(dy * INV_BOX) * BOXF;
    dz -= rintf(dz * INV_BOX) * BOXF;
    const float r2 = fmaf(dx, dx, fmaf(dy, dy, dz * dz));

    const bool  ok = valid && (r2 < CUT2);
    const float we = ok ? wbase : 0.0f;
    const float wf = (ok && r2 > 1.0f) ? wbase : 0.0f;

    const float r2c  = fmaxf(r2, 1.0f);
    const float dinv = rsqrtf(r2c);
    const float dij  = r2c * dinv;

    const float invrh = __fdividef(1.0f, rh);
    const float e     = __expf((sg - dij) * invrh);

    const float inv2 = dinv * dinv;
    const float inv6 = inv2 * inv2 * inv2;
    const float inv8 = inv6 * inv2;

    const float ae = a * e;
    const float pe = fmaf(dd, inv8, fmaf(-c, inv6, ae));
    en = fmaf(we, pe, en);                       // unordered pair counted once

    float g = fmaf(6.0f * c, inv8,
                   fmaf(-8.0f * dd, inv8 * inv2,
                        -(ae * invrh) * dinv));
    g *= wf;
    gx = g * dx; gy = g * dy; gz = g * dz;
}

__global__ __launch_bounds__(TPB)
void bmh_tile_kernel(const float* __restrict__ coords,
                     const float* __restrict__ A,
                     const float* __restrict__ C,
                     const float* __restrict__ D,
                     const float* __restrict__ RHO,
                     const float* __restrict__ SIG)
{
    // decode blockIdx -> tile pair (ti <= tj)
    int k = blockIdx.x, ti = 0, rem = NTILE;
    while (k >= rem) { k -= rem; ++ti; --rem; }
    const int tj   = ti + k;
    const bool diag = (ti == tj);

    const int t    = threadIdx.x;
    const int lane = t & 31;
    const int w    = t >> 5;                 // warp 0..15

    // this lane owns columns jc0..jc0+7 of tile tj
    const int jc0 = 8 * lane;
    const int jg0 = tj * T + jc0;
    const float wbase = ((ti >> 1) == (tj >> 1)) ? 1.0f : 2.0f;  // same 512-block?

    // column coords: 24 contiguous floats = 6 float4
    float xj[8], yj[8], zj[8];
    {
        const float4* cf = (const float4*)(coords + 3 * (size_t)jg0);
        float v[24];
        #pragma unroll
        for (int q = 0; q < 6; ++q) {
            const float4 f = __ldg(cf + q);
            v[4 * q + 0] = f.x; v[4 * q + 1] = f.y; v[4 * q + 2] = f.z; v[4 * q + 3] = f.w;
        }
        #pragma unroll
        for (int c = 0; c < 8; ++c) { xj[c] = v[3 * c]; yj[c] = v[3 * c + 1]; zj[c] = v[3 * c + 2]; }
    }
    const int locj0 = jg0 & (BLOCK_SZ - 1);

    __shared__ float frow[T][3];              // row-force results (one writer per row)
    __shared__ float fcolp[16][T * 3];        // per-warp column-force partials
    __shared__ float esm[TPB / 32];

    float fjx[8], fjy[8], fjz[8];
    #pragma unroll
    for (int c = 0; c < 8; ++c) { fjx[c] = 0.f; fjy[c] = 0.f; fjz[c] = 0.f; }
    float en = 0.f;

    const size_t rowstart = (size_t)(ti * T) * NATOMS + tj * T + jc0;

    #pragma unroll 2
    for (int s = 0; s < T / 16; ++s) {
        const int i  = s * 16 + w;            // row within tile (warp-exclusive)
        const int ig = ti * T + i;
        const size_t off = rowstart + (size_t)i * NATOMS;

        const float4 aA = __ldg((const float4*)(A   + off));
        const float4 aB = __ldg((const float4*)(A   + off + 4));
        const float4 cA = __ldg((const float4*)(C   + off));
        const float4 cB = __ldg((const float4*)(C   + off + 4));
        const float4 dA = __ldg((const float4*)(D   + off));
        const float4 dB = __ldg((const float4*)(D   + off + 4));
        const float4 rA = __ldg((const float4*)(RHO + off));
        const float4 rB = __ldg((const float4*)(RHO + off + 4));
        const float4 sA = __ldg((const float4*)(SIG + off));
        const float4 sB = __ldg((const float4*)(SIG + off + 4));

        const float xi = __ldg(&coords[3 * ig + 0]);
        const float yi = __ldg(&coords[3 * ig + 1]);
        const float zi = __ldg(&coords[3 * ig + 2]);
        const int loci = ig & (BLOCK_SZ - 1);

        float av[8] = {aA.x, aA.y, aA.z, aA.w, aB.x, aB.y, aB.z, aB.w};
        float cv[8] = {cA.x, cA.y, cA.z, cA.w, cB.x, cB.y, cB.z, cB.w};
        float dv[8] = {dA.x, dA.y, dA.z, dA.w, dB.x, dB.y, dB.z, dB.w};
        float rv[8] = {rA.x, rA.y, rA.z, rA.w, rB.x, rB.y, rB.z, rB.w};
        float sv[8] = {sA.x, sA.y, sA.z, sA.w, sB.x, sB.y, sB.z, sB.w};

        float rx = 0.f, ry = 0.f, rz = 0.f;
        #pragma unroll
        for (int c = 0; c < 8; ++c) {
            float gx, gy, gz;
            const bool ok = (loci != locj0 + c) && (!diag || i < jc0 + c);
            pm(xi - xj[c], yi - yj[c], zi - zj[c],
               av[c], cv[c], dv[c], rv[c], sv[c], ok, wbase, en, gx, gy, gz);
            rx += gx; ry += gy; rz += gz;
            fjx[c] -= gx; fjy[c] -= gy; fjz[c] -= gz;
        }

        // row force: shuffle-tree reduce across 32 lanes (256 columns)
        rx = warp_sum(rx); ry = warp_sum(ry); rz = warp_sum(rz);
        if (lane == 0) { frow[i][0] = rx; frow[i][1] = ry; frow[i][2] = rz; }
    }

    // stash per-warp column partials
    {
        float* cp = &fcolp[w][jc0 * 3];
        #pragma unroll
        for (int c = 0; c < 8; ++c) {
            cp[3 * c + 0] = fjx[c];
            cp[3 * c + 1] = fjy[c];
            cp[3 * c + 2] = fjz[c];
        }
    }

    // energy partial
    en = warp_sum(en);
    if (lane == 0) esm[w] = en;
    __syncthreads();

    if (t < T) {
        // row atom i=t of tile ti -> slot tj (diag merges column force too)
        float rx = frow[t][0], ry = frow[t][1], rz = frow[t][2];
        if (diag) {
            #pragma unroll
            for (int ww = 0; ww < 16; ++ww) {
                rx += fcolp[ww][t * 3 + 0];
                ry += fcolp[ww][t * 3 + 1];
                rz += fcolp[ww][t * 3 + 2];
            }
        }
        float* dst = g_fpart + ((size_t)tj * NATOMS + ti * T + t) * 3;
        dst[0] = rx; dst[1] = ry; dst[2] = rz;
    } else if (!diag) {
        // column atom c of tile tj -> slot ti
        const int c = t - T;
        float cx = 0.f, cy = 0.f, cz = 0.f;
        #pragma unroll
        for (int ww = 0; ww < 16; ++ww) {
            cx += fcolp[ww][c * 3 + 0];
            cy += fcolp[ww][c * 3 + 1];
            cz += fcolp[ww][c * 3 + 2];
        }
        float* dst = g_fpart + ((size_t)ti * NATOMS + tj * T + c) * 3;
        dst[0] = cx; dst[1] = cy; dst[2] = cz;
    }

    if (t < 32) {
        float v = (t < TPB / 32) ? esm[t] : 0.f;
        v = warp_sum(v);
        if (t == 0) g_ecta[blockIdx.x] = v;
    }
}

// fast reduce: 6 CTAs x 512 threads cover 3072 float4 outputs; CTA 6 does energy
#define RTPB 512
#define NQUAD (NATOMS * 3 / 4)   // 3072 float4s per slot

__global__ __launch_bounds__(RTPB)
void bmh_reduce_kernel(float* __restrict__ out)
{
    const int tid = threadIdx.x;
    const int b   = blockIdx.x;

    if (b < 6) {
        const int q = b * RTPB + tid;         // 0..3071
        const float4* fp = (const float4*)g_fpart;
        float sx = 0.f, sy = 0.f, sz = 0.f, sw = 0.f;
        #pragma unroll
        for (int p = 0; p < NTILE; ++p) {
            const float4 v = fp[(size_t)p * NQUAD + q];   // independent: MLP = 16
            sx += v.x; sy += v.y; sz += v.z; sw += v.w;
        }
        float* dst = out + 1 + q * 4;
        dst[0] = sx; dst[1] = sy; dst[2] = sz; dst[3] = sw;
    } else {
        // energy: fixed-order double sum over 136 CTA partials
        double s = (tid < NPAIR) ? (double)g_ecta[tid] : 0.0;
        __shared__ double sd[RTPB];
        sd[tid] = s;
        __syncthreads();
        #pragma unroll
        for (int o = RTPB / 2; o > 0; o >>= 1) {
            if (tid < o) sd[tid] += sd[tid + o];
            __syncthreads();
        }
        if (tid == 0) out[0] = (float)sd[0];
    }
}

extern "C" void kernel_launch(void* const* d_in, const int* in_sizes, int n_in,
                              void* d_out, int out_size)
{
    const float* coords = (const float*)d_in[0];
    // d_in[1] = q (computed-but-unused upstream; faithfully ignored)
    const float* A   = (const float*)d_in[2];
    const float* C   = (const float*)d_in[3];
    const float* D   = (const float*)d_in[4];
    const float* RHO = (const float*)d_in[5];
    const float* SIG = (const float*)d_in[6];
    float* out = (float*)d_out;

    bmh_tile_kernel<<<NPAIR, TPB>>>(coords, A, C, D, RHO, SIG);
    bmh_reduce_kernel<<<7, RTPB>>>(out);
}